// round 3
// baseline (speedup 1.0000x reference)
#include <cuda_runtime.h>
#include <cuda_fp16.h>

#define BATCH 32768
#define NF 64
#define NB 33          // bounds per feature
#define NP 32          // pieces = NB-1
#define E  64          // embedding per feature

#define FG   4                 // features per block
#define NFG  (NF / FG)         // 16 feature groups
#define RPB  64                // rows per block
#define NRG  (BATCH / RPB)     // 512 row groups

// Packed table, 256B per (f,j): 16 float4 chunks. Chunk q (outputs 4q..4q+3)
// holds halves (c0,c1,w0,w1,c2,c3,w2,w3) so a float4 load feeds 2x HFMA2:
//   .x=(c0,c1) .y=(w0,w1) .z=(c2,c3) .w=(w2,w3)
// c[f][j][e] = b[f][e] + sum_{i<j} W[f][i][e];  w[f][j][e] = W[f][j][e] (0 at j=32)
__device__ float4 g_P4[NF * NB * 16];   // 270 KB (fp16)

// ---------------------------------------------------------------------------
// Prep: one thread per (f, e). Writes individual halves (2B stores, no races).
// ---------------------------------------------------------------------------
__global__ void pwl_prep(const float* __restrict__ W, const float* __restrict__ bias) {
    int idx = blockIdx.x * blockDim.x + threadIdx.x;
    if (idx >= NF * E) return;
    int f = idx >> 6;
    int e = idx & 63;
    int l = e & 3;
    int hc = ((e >> 2) << 3) + (l & 1) + ((l & 2) << 1);  // c half index within 128-half row
    __half* gp = reinterpret_cast<__half*>(g_P4);
    float c = bias[f * E + e];
#pragma unroll
    for (int j = 0; j < NP; j++) {
        float w = W[(f * NP + j) * E + e];
        __half* row = gp + ((f * NB + j) << 7);
        row[hc]     = __float2half_rn(c);
        row[hc + 2] = __float2half_rn(w);
        c += w;
    }
    __half* row = gp + ((f * NB + NP) << 7);
    row[hc]     = __float2half_rn(c);
    row[hc + 2] = __half(0.0f);
}

// ---------------------------------------------------------------------------
// Main: block = (feature group fg of 4 features) x (64 rows). 512 threads.
//   1. copy table slice (33.8 KB) + bounds slice to smem
//   2. compute (table offset, frac-as-half2) for all 256 (row, feat) pairs
//   3. 8 iterations: each thread emits one float4 (LDS.128 -> HFMA2 -> STG.128)
// ---------------------------------------------------------------------------
__global__ __launch_bounds__(512, 4)
void pwl_main(const float* __restrict__ X,
              const float* __restrict__ bounds,
              float* __restrict__ out) {
    __shared__ float4   s_tab[FG * NB * 16];   // 33792 B
    __shared__ float    s_bnd[FG * NB];        // 528 B
    __shared__ int      s_off[RPB * FG];       // 1024 B (float4 offset into s_tab)
    __shared__ unsigned s_fr[RPB * FG];        // 1024 B (frac replicated as half2)

    int t  = threadIdx.x;
    int fg = blockIdx.x >> 9;          // 0..15
    int rg = blockIdx.x & 511;         // 0..511
    int rowbase = rg * RPB;

    // ---- load table slice + bounds slice ----
    const float4* gsl = g_P4 + fg * (FG * NB * 16);
#pragma unroll
    for (int i = t; i < FG * NB * 16; i += 512) s_tab[i] = gsl[i];
    if (t < FG * NB) {
        int f_l = t / NB, k = t % NB;
        s_bnd[t] = bounds[(fg * FG + f_l) * NB + k];
    }
    __syncthreads();

    // ---- per-(row, feature) piece index + frac ----
    if (t < RPB * FG) {
        int r   = t >> 2;
        int f_l = t & 3;
        float x = X[(rowbase + r) * NF + fg * FG + f_l];
        const float* bd = s_bnd + f_l * NB;
        int j = 0;
#pragma unroll
        for (int k = 1; k <= NP; k++) j += (x >= bd[k]) ? 1 : 0;
        float frac = 0.0f;
        if (j < NP) {
            float lo = bd[j], hi = bd[j + 1];
            frac = fminf(fmaxf((x - lo) / (hi - lo), 0.0f), 1.0f);
        }
        s_off[t] = (f_l * NB + j) << 4;
        __half2 h2 = __float2half2_rn(frac);
        s_fr[t] = *reinterpret_cast<unsigned*>(&h2);
    }
    __syncthreads();

    // ---- emit 64 rows x 256 floats ----
    int slot = t & 63;                 // 0..63: f_l = slot>>4, e4 = slot&15
    int f_l  = slot >> 4;
    int e4   = slot & 15;
    int rl   = t >> 6;                 // 0..7
    float4* out4 = reinterpret_cast<float4*>(out);
    const __half2 zero2 = __float2half2_rn(0.0f);

#pragma unroll
    for (int it = 0; it < 8; it++) {
        int r   = it * 8 + rl;
        int ix  = r * FG + f_l;
        int off = s_off[ix];
        unsigned fru = s_fr[ix];
        __half2 f2 = *reinterpret_cast<__half2*>(&fru);

        float4 p = s_tab[off + e4];
        __half2 c01 = *reinterpret_cast<__half2*>(&p.x);
        __half2 w01 = *reinterpret_cast<__half2*>(&p.y);
        __half2 c23 = *reinterpret_cast<__half2*>(&p.z);
        __half2 w23 = *reinterpret_cast<__half2*>(&p.w);

        __half2 r01 = __hmax2(__hfma2(f2, w01, c01), zero2);
        __half2 r23 = __hmax2(__hfma2(f2, w23, c23), zero2);
        float2 o01 = __half22float2(r01);
        float2 o23 = __half22float2(r23);

        size_t orow = (size_t)(rowbase + r) * 1024 + fg * (FG * 16) + slot;
        __stcs(out4 + orow, make_float4(o01.x, o01.y, o23.x, o23.y));
    }
}

extern "C" void kernel_launch(void* const* d_in, const int* in_sizes, int n_in,
                              void* d_out, int out_size) {
    const float* X      = (const float*)d_in[0];   // (32768, 64)
    const float* bounds = (const float*)d_in[1];   // (64, 33)
    const float* W      = (const float*)d_in[2];   // (64, 32, 64)
    const float* bias   = (const float*)d_in[3];   // (64, 64)
    float* out = (float*)d_out;                    // (32768, 4096)

    pwl_prep<<<(NF * E + 255) / 256, 256>>>(W, bias);
    pwl_main<<<NFG * NRG, 512>>>(X, bounds, out);
}

// round 4
// speedup vs baseline: 1.9183x; 1.9183x over previous
#include <cuda_runtime.h>
#include <cuda_fp16.h>

#define BATCH 32768
#define NF 64
#define NB 33          // bounds per feature
#define NP 32          // pieces = NB-1
#define E  64          // embedding per feature

// Packed table, 256B per (f,j): 16 float4 chunks. Chunk q (outputs 4q..4q+3)
// holds halves (c0,c1,w0,w1,c2,c3,w2,w3):
//   .x=(c0,c1) .y=(w0,w1) .z=(c2,c3) .w=(w2,w3)  -> 2x HFMA2 per chunk.
// c[f][j][e] = b[f][e] + sum_{i<j} W[f][i][e];  w[f][j][e] = W[f][j][e] (0 at j=32)
__device__ float4 g_P4[NF * NB * 16];            // 540 KB

// Transposed bounds for coalesced search: bT[k][f]
__device__ float g_bT[NB * NF];

// ---------------------------------------------------------------------------
// Prep: one thread per (f, e); 2B half stores, no races. Also transpose bounds.
// ---------------------------------------------------------------------------
__global__ void pwl_prep(const float* __restrict__ W,
                         const float* __restrict__ bias,
                         const float* __restrict__ bounds) {
    int idx = blockIdx.x * blockDim.x + threadIdx.x;
    if (idx < NB * NF) {
        int k = idx >> 6;
        int f = idx & 63;
        g_bT[idx] = bounds[f * NB + k];
    }
    if (idx >= NF * E) return;
    int f = idx >> 6;
    int e = idx & 63;
    int l = e & 3;
    int hc = ((e >> 2) << 3) + (l & 1) + ((l & 2) << 1);
    __half* gp = reinterpret_cast<__half*>(g_P4);
    float c = bias[f * E + e];
#pragma unroll
    for (int j = 0; j < NP; j++) {
        float w = W[(f * NP + j) * E + e];
        __half* row = gp + ((f * NB + j) << 7);
        row[hc]     = __float2half_rn(c);
        row[hc + 2] = __float2half_rn(w);
        c += w;
    }
    __half* row = gp + ((f * NB + NP) << 7);
    row[hc]     = __float2half_rn(c);
    row[hc + 2] = __half(0.0f);
}

// ---------------------------------------------------------------------------
// Main: one block per batch row, 256 threads, 4 float4 slots per thread.
//   Phase 1: threads 0..63 -> (float4 table base, frac as half2).
//   Phase 2: per slot: LDG.128 (L1/L2-resident table) -> 2xHFMA2/HMAX2 ->
//            4 CVT -> STG.128 streaming.
// ---------------------------------------------------------------------------
__global__ __launch_bounds__(256, 8)
void pwl_main(const float* __restrict__ X,
              float* __restrict__ out) {
    __shared__ int      s_base[NF];
    __shared__ unsigned s_fr[NF];

    int b = blockIdx.x;
    int t = threadIdx.x;

    if (t < NF) {
        float x = X[b * NF + t];
        int j = 0;
#pragma unroll
        for (int k = 1; k <= NP; k++) j += (x >= g_bT[k * NF + t]) ? 1 : 0;
        float frac = 0.0f;
        if (j < NP) {
            float lo = g_bT[j * NF + t];
            float hi = g_bT[(j + 1) * NF + t];
            frac = fminf(fmaxf((x - lo) / (hi - lo), 0.0f), 1.0f);
        }
        s_base[t] = (t * NB + j) << 4;      // float4 index of P[f][j] chunk 0
        __half2 h2 = __float2half2_rn(frac);
        s_fr[t] = *reinterpret_cast<unsigned*>(&h2);
    }
    __syncthreads();

    float4* out4 = reinterpret_cast<float4*>(out + (size_t)b * (NF * E));
    const __half2 zero2 = __float2half2_rn(0.0f);

#pragma unroll
    for (int rep = 0; rep < 4; rep++) {
        int i  = t + rep * 256;             // 0..1023 float4 slots
        int f  = i >> 4;                    // 16 float4 per feature
        int e4 = i & 15;
        int base     = s_base[f];
        unsigned fru = s_fr[f];
        __half2 f2 = *reinterpret_cast<__half2*>(&fru);

        float4 p = g_P4[base + e4];
        __half2 c01 = *reinterpret_cast<__half2*>(&p.x);
        __half2 w01 = *reinterpret_cast<__half2*>(&p.y);
        __half2 c23 = *reinterpret_cast<__half2*>(&p.z);
        __half2 w23 = *reinterpret_cast<__half2*>(&p.w);

        __half2 r01 = __hmax2(__hfma2(f2, w01, c01), zero2);
        __half2 r23 = __hmax2(__hfma2(f2, w23, c23), zero2);
        float2 o01 = __half22float2(r01);
        float2 o23 = __half22float2(r23);

        __stcs(out4 + i, make_float4(o01.x, o01.y, o23.x, o23.y));
    }
}

extern "C" void kernel_launch(void* const* d_in, const int* in_sizes, int n_in,
                              void* d_out, int out_size) {
    const float* X      = (const float*)d_in[0];   // (32768, 64)
    const float* bounds = (const float*)d_in[1];   // (64, 33)
    const float* W      = (const float*)d_in[2];   // (64, 32, 64)
    const float* bias   = (const float*)d_in[3];   // (64, 64)
    float* out = (float*)d_out;                    // (32768, 4096)

    pwl_prep<<<(NF * E + 255) / 256, 256>>>(W, bias, bounds);
    pwl_main<<<BATCH, 256>>>(X, out);
}